// round 17
// baseline (speedup 1.0000x reference)
#include <cuda_runtime.h>

// AverageSpanExtractor: out[b,n,:] = mean(seq[b, start:end, :]) * mask[b,n]
// seq: [B,S,D] f32; spans: [B,N,2] i32; mask: [B,N] i32; out: [B,N,D] f32.
//
// Single-kernel schedule-for-locality. Classic placement: smid = LUT[bid%148]
// (any permutation) => all CTAs with equal bid%148 share one SM. Grid 1480 =
// 148 classes x 10 CTAs, all co-resident (128 thr, <=42 regs) => spin grid
// barriers are safe. Phases: zero counters | bin spans by sequence position
// into 148 groups | reduce, CTA class r serving group r. Each SM's gather is
// confined to a ~111-cell window -> rows L1-resident, L2 sees ~once-per-SM
// traffic (~60MB vs the 188MB that pins flat kernels at the LTS cap).

#define MAX_W    20
#define DIM      512
#define D4       128
#define NSM      148
#define CPB      10                  // CTAs per mod-148 class
#define GRID     (NSM * CPB)         // 1480
#define SLOT_CAP 128                 // Poisson(55.4); >128 impossible in practice

__device__ int  g_count[NSM];
__device__ int4 g_slots[NSM * SLOT_CAP];  // (span_id, cell, width, mask)
__device__ int  g_bar[2];                 // epoch-accumulating barrier counters

__device__ __forceinline__ void grid_barrier(int* ctr)
{
    __syncthreads();
    if (threadIdx.x == 0) {
        __threadfence();
        const int ticket = atomicAdd(ctr, 1);
        const int target = (ticket / GRID + 1) * GRID;
        while (*(volatile int*)ctr < target) { }
    }
    __syncthreads();
    __threadfence();
}

__global__ __launch_bounds__(128, 12)
void avg_span_kernel(const float* __restrict__ seq,
                     const int* __restrict__ spans,
                     const int* __restrict__ mask,
                     float* __restrict__ out,
                     int S, int N, int total, int total_cells)
{
    const int c = blockIdx.x;
    const int t = threadIdx.x;

    // ---- phase 0: zero group counters ----
    if (c == 0 && t < NSM) g_count[t] = 0;
    grid_barrier(&g_bar[0]);

    // ---- phase 1: bin spans into mod-148 groups by sequence position ----
    const int gt = c * 128 + t;
    if (gt < total) {
        const int2 se = ((const int2*)spans)[gt];
        const int b = gt / N;
        const int cell = b * S + se.x;
        int w = se.y - se.x;
        w = (w < MAX_W) ? w : MAX_W;             // reference's static clamp
        w = (w > 0) ? w : 1;
        const int g = (int)(((long long)cell * NSM) / total_cells);
        const int slot = atomicAdd(&g_count[g], 1);
        if (slot < SLOT_CAP) {
            g_slots[g * SLOT_CAP + slot] = make_int4(gt, cell, w, mask[gt]);
        } else {
            // statistically impossible overflow: direct reduce (correct)
            const float scale = (float)mask[gt] / (float)w;
            const float* src = seq + (long long)cell * DIM;
            float* o = out + (long long)gt * DIM;
            for (int d = 0; d < DIM; ++d) {
                float a = 0.f;
                for (int r = 0; r < w; ++r) a += src[r * DIM + d];
                o[d] = a * scale;
            }
        }
    }
    grid_barrier(&g_bar[1]);

    // ---- phase 2: reduce; class r = c % NSM stays on one SM ----
    const int r = c % NSM;
    const int j0 = c / NSM;                      // 0..CPB-1
    const int cnt = min(g_count[r], SLOT_CAP);

    for (int i = j0; i < cnt; i += CPB) {
        const int4 e = g_slots[r * SLOT_CAP + i];   // (span_id, cell, w, mask)

        const float4* p = (const float4*)seq + (long long)e.y * D4 + t;
        float4 acc = make_float4(0.f, 0.f, 0.f, 0.f);

        #pragma unroll 4
        for (int rr = 0; rr < e.z; ++rr) {
            float4 v = *p;
            p += D4;
            acc.x += v.x; acc.y += v.y; acc.z += v.z; acc.w += v.w;
        }

        const float s = (float)e.w / (float)e.z;
        acc.x *= s; acc.y *= s; acc.z *= s; acc.w *= s;

        float4* o = (float4*)out + (long long)e.x * D4;
        o[t] = acc;
    }
}

extern "C" void kernel_launch(void* const* d_in, const int* in_sizes, int n_in,
                              void* d_out, int out_size)
{
    const float* seq  = (const float*)d_in[0];
    const int* spans  = (const int*)d_in[1];
    const int* mask   = (const int*)d_in[2];
    float* out        = (float*)d_out;

    const int S = 2048;
    const int B = in_sizes[0] / (S * DIM);       // 8
    const int N = in_sizes[2] / B;               // 1024
    const int total = B * N;                     // 8192
    const int total_cells = B * S;               // 16384

    avg_span_kernel<<<GRID, 128>>>(seq, spans, mask, out,
                                   S, N, total, total_cells);
}